// round 5
// baseline (speedup 1.0000x reference)
#include <cuda_runtime.h>
#include <cuda_fp16.h>
#include <cuda_bf16.h>

#define DIMV 33
#define DIM2 (DIMV*DIMV)        // 1089
#define DIM3 (DIMV*DIMV*DIMV)   // 35937
#define HW   (2048*2048)        // 4194304 = 2^22

#define AB_BYTES   (DIM3 * 4)            // half2 per lattice point: 143748 B
#define C_WORDS    ((DIM3 + 1) / 2)      // half array copied as uint32: 17969 words
#define C_BYTES    (C_WORDS * 4)         // 71876 B (padded to even half count)
#define SMEM_BYTES (AB_BYTES + C_BYTES)  // 215624 B  (< 227 KB opt-in limit)

#define NTHREADS 768
#define NBLOCKS  148
#define NGROUPS  (HW)                    // 4*HW pixels / 4 px per group = 2^22 groups
#define GPI      (HW / 4)                // groups per image = 2^20

// Global staging for the fp16-compressed, channel-split LUT.
__device__ __half2 g_AB[DIM3];           // (c0, c1) per lattice point
__device__ __half  g_C [DIM3 + 1];       // c2 per lattice point (+pad for 4B copy)

__global__ void repack_lut_kernel(const float* __restrict__ lut) {
    int i = blockIdx.x * blockDim.x + threadIdx.x;
    if (i < DIM3) {
        g_AB[i] = __floats2half2_rn(lut[i], lut[i + DIM3]);
        g_C[i]  = __float2half_rn(lut[i + 2 * DIM3]);
    }
    if (i == 0) g_C[DIM3] = __float2half_rn(0.0f);
}

__device__ __forceinline__ void load_quad(const float* __restrict__ x, int g,
                                          float4& rv, float4& gv, float4& bv) {
    int bimg = g >> 20;                  // GPI = 2^20
    int q    = (g & (GPI - 1)) << 2;
    const float* xb = x + (size_t)bimg * 3 * HW + q;
    rv = *(const float4*)(xb);
    gv = *(const float4*)(xb + HW);
    bv = *(const float4*)(xb + 2 * HW);
}

__global__ void __launch_bounds__(NTHREADS, 1)
lut3d_smem_kernel(const float* __restrict__ x, float* __restrict__ out) {
    extern __shared__ char smem[];
    __half2* sAB = (__half2*)smem;
    __half*  sC  = (__half*)(smem + AB_BYTES);

    // Cooperative LUT copy into shared memory (4B granularity).
    {
        const unsigned* gab = (const unsigned*)g_AB;
        unsigned* dab = (unsigned*)sAB;
        for (int i = threadIdx.x; i < DIM3; i += NTHREADS) dab[i] = __ldg(gab + i);
        const unsigned* gc = (const unsigned*)g_C;
        unsigned* dc = (unsigned*)sC;
        for (int i = threadIdx.x; i < C_WORDS; i += NTHREADS) dc[i] = __ldg(gc + i);
    }
    __syncthreads();

    const int stride = NBLOCKS * NTHREADS;
    int g = blockIdx.x * NTHREADS + threadIdx.x;

    float4 rv, gv, bv;
    bool valid = g < NGROUPS;
    if (valid) load_quad(x, g, rv, gv, bv);

    while (valid) {
        // ---- software pipeline: prefetch next group's input before the LDS burst
        int gn = g + stride;
        bool vn = gn < NGROUPS;
        float4 rvn, gvn, bvn;
        if (vn) load_quad(x, gn, rvn, gvn, bvn);

        float rr4[4] = {rv.x, rv.y, rv.z, rv.w};
        float gg4[4] = {gv.x, gv.y, gv.z, gv.w};
        float bb4[4] = {bv.x, bv.y, bv.z, bv.w};

        float o0[4], o1[4], o2[4];

        #pragma unroll
        for (int k = 0; k < 4; k++) {
            float rr = rr4[k] * 32.0f;
            float gg = gg4[k] * 32.0f;
            float bb = bb4[k] * 32.0f;

            int r0 = __float2int_rd(rr); r0 = min(max(r0, 0), 31);
            int g0 = __float2int_rd(gg); g0 = min(max(g0, 0), 31);
            int b0 = __float2int_rd(bb); b0 = min(max(b0, 0), 31);

            float fr = rr - (float)r0;
            float fg = gg - (float)g0;
            float fb = bb - (float)b0;

            int i000 = (b0 * DIMV + g0) * DIMV + r0;
            int i010 = i000 + DIMV;
            int i100 = i000 + DIM2;
            int i110 = i100 + DIMV;

            float2 v000 = __half22float2(sAB[i000]);
            float2 v001 = __half22float2(sAB[i000 + 1]);
            float2 v010 = __half22float2(sAB[i010]);
            float2 v011 = __half22float2(sAB[i010 + 1]);
            float2 v100 = __half22float2(sAB[i100]);
            float2 v101 = __half22float2(sAB[i100 + 1]);
            float2 v110 = __half22float2(sAB[i110]);
            float2 v111 = __half22float2(sAB[i110 + 1]);

            float c000 = __half2float(sC[i000]);
            float c001 = __half2float(sC[i000 + 1]);
            float c010 = __half2float(sC[i010]);
            float c011 = __half2float(sC[i010 + 1]);
            float c100 = __half2float(sC[i100]);
            float c101 = __half2float(sC[i100 + 1]);
            float c110 = __half2float(sC[i110]);
            float c111 = __half2float(sC[i110 + 1]);

            float fr0 = 1.0f - fr, fg0 = 1.0f - fg, fb0 = 1.0f - fb;

            float wb0g0 = fb0 * fg0;
            float wb0g1 = fb0 * fg;
            float wb1g0 = fb  * fg0;
            float wb1g1 = fb  * fg;

            float w000 = wb0g0 * fr0, w001 = wb0g0 * fr;
            float w010 = wb0g1 * fr0, w011 = wb0g1 * fr;
            float w100 = wb1g0 * fr0, w101 = wb1g0 * fr;
            float w110 = wb1g1 * fr0, w111 = wb1g1 * fr;

            float a0 = w000 * v000.x;
            float a1 = w000 * v000.y;
            float a2 = w000 * c000;
            a0 = fmaf(w001, v001.x, a0); a1 = fmaf(w001, v001.y, a1); a2 = fmaf(w001, c001, a2);
            a0 = fmaf(w010, v010.x, a0); a1 = fmaf(w010, v010.y, a1); a2 = fmaf(w010, c010, a2);
            a0 = fmaf(w011, v011.x, a0); a1 = fmaf(w011, v011.y, a1); a2 = fmaf(w011, c011, a2);
            a0 = fmaf(w100, v100.x, a0); a1 = fmaf(w100, v100.y, a1); a2 = fmaf(w100, c100, a2);
            a0 = fmaf(w101, v101.x, a0); a1 = fmaf(w101, v101.y, a1); a2 = fmaf(w101, c101, a2);
            a0 = fmaf(w110, v110.x, a0); a1 = fmaf(w110, v110.y, a1); a2 = fmaf(w110, c110, a2);
            a0 = fmaf(w111, v111.x, a0); a1 = fmaf(w111, v111.y, a1); a2 = fmaf(w111, c111, a2);

            o0[k] = a0;
            o1[k] = a1;
            o2[k] = a2;
        }

        {
            int bimg = g >> 20;
            int q    = (g & (GPI - 1)) << 2;
            float* ob = out + (size_t)bimg * 3 * HW + q;
            *(float4*)(ob)          = make_float4(o0[0], o0[1], o0[2], o0[3]);
            *(float4*)(ob + HW)     = make_float4(o1[0], o1[1], o1[2], o1[3]);
            *(float4*)(ob + 2 * HW) = make_float4(o2[0], o2[1], o2[2], o2[3]);
        }

        rv = rvn; gv = gvn; bv = bvn;
        g = gn;
        valid = vn;
    }
}

extern "C" void kernel_launch(void* const* d_in, const int* in_sizes, int n_in,
                              void* d_out, int out_size) {
    const float* x   = (const float*)d_in[0];   // (4, 3, 2048, 2048)
    const float* lut = (const float*)d_in[1];   // (3, 33, 33, 33)
    float* out = (float*)d_out;

    cudaFuncSetAttribute(lut3d_smem_kernel,
                         cudaFuncAttributeMaxDynamicSharedMemorySize, SMEM_BYTES);

    repack_lut_kernel<<<(DIM3 + 255) / 256, 256>>>(lut);

    lut3d_smem_kernel<<<NBLOCKS, NTHREADS, SMEM_BYTES>>>(x, out);
}

// round 6
// speedup vs baseline: 1.4709x; 1.4709x over previous
#include <cuda_runtime.h>
#include <cuda_fp16.h>
#include <cuda_bf16.h>

#define DIMV 33
#define DIM2 (DIMV*DIMV)        // 1089
#define DIM3 (DIMV*DIMV*DIMV)   // 35937
#define HW   (2048*2048)        // 4194304 = 2^22

#define AB_BYTES   (DIM3 * 4)            // half2 per lattice point: 143748 B
#define C_WORDS    ((DIM3 + 1) / 2)      // half array copied as uint32
#define C_BYTES    (C_WORDS * 4)         // 71876 B
#define SMEM_BYTES (AB_BYTES + C_BYTES)  // 215624 B (< 227 KB opt-in limit)

#define NTHREADS 1024
#define NBLOCKS  148
#define GPI      (HW / 2)                // pixel-pairs per image = 2^21
#define NGROUPS  (4 * GPI)               // total pixel-pairs = 2^23

// Global staging for the fp16-compressed, channel-split LUT.
__device__ __half2 g_AB[DIM3];           // (c0, c1) per lattice point
__device__ __half  g_C [DIM3 + 1];       // c2 per lattice point (+pad for 4B copy)

__global__ void repack_lut_kernel(const float* __restrict__ lut) {
    int i = blockIdx.x * blockDim.x + threadIdx.x;
    if (i < DIM3) {
        g_AB[i] = __floats2half2_rn(lut[i], lut[i + DIM3]);
        g_C[i]  = __float2half_rn(lut[i + 2 * DIM3]);
    }
    if (i == 0) g_C[DIM3] = __float2half_rn(0.0f);
}

__device__ __forceinline__ void load_pair(const float* __restrict__ x, int g,
                                          float2& rv, float2& gv, float2& bv) {
    int bimg = g >> 21;                  // GPI = 2^21
    int q    = (g & (GPI - 1)) << 1;
    const float* xb = x + (size_t)bimg * 3 * HW + q;
    rv = *(const float2*)(xb);
    gv = *(const float2*)(xb + HW);
    bv = *(const float2*)(xb + 2 * HW);
}

__global__ void __launch_bounds__(NTHREADS, 1)
lut3d_smem_kernel(const float* __restrict__ x, float* __restrict__ out) {
    extern __shared__ char smem[];
    __half2* sAB = (__half2*)smem;
    __half*  sC  = (__half*)(smem + AB_BYTES);

    // Cooperative LUT copy into shared memory (4B granularity).
    {
        const unsigned* gab = (const unsigned*)g_AB;
        unsigned* dab = (unsigned*)sAB;
        for (int i = threadIdx.x; i < DIM3; i += NTHREADS) dab[i] = __ldg(gab + i);
        const unsigned* gc = (const unsigned*)g_C;
        unsigned* dc = (unsigned*)sC;
        for (int i = threadIdx.x; i < C_WORDS; i += NTHREADS) dc[i] = __ldg(gc + i);
    }
    __syncthreads();

    const int stride = NBLOCKS * NTHREADS;
    int g = blockIdx.x * NTHREADS + threadIdx.x;

    float2 rv, gv, bv;
    load_pair(x, g, rv, gv, bv);         // stride < NGROUPS, so first g always valid

    for (;;) {
        // ---- software pipeline: prefetch next group's inputs (clamped addr, no predication)
        int gn = g + stride;
        int gp = (gn < NGROUPS) ? gn : g;
        float2 rvn, gvn, bvn;
        load_pair(x, gp, rvn, gvn, bvn);

        float rr2[2] = {rv.x, rv.y};
        float gg2[2] = {gv.x, gv.y};
        float bb2[2] = {bv.x, bv.y};
        float o0[2], o1[2], o2[2];

        #pragma unroll
        for (int k = 0; k < 2; k++) {
            float rr = rr2[k] * 32.0f;
            float gg = gg2[k] * 32.0f;
            float bb = bb2[k] * 32.0f;

            int r0 = __float2int_rd(rr); r0 = min(max(r0, 0), 31);
            int g0 = __float2int_rd(gg); g0 = min(max(g0, 0), 31);
            int b0 = __float2int_rd(bb); b0 = min(max(b0, 0), 31);

            float fr = rr - (float)r0;
            float fg = gg - (float)g0;
            float fb = bb - (float)b0;

            int i000 = (b0 * DIMV + g0) * DIMV + r0;
            int i010 = i000 + DIMV;
            int i100 = i000 + DIM2;
            int i110 = i100 + DIMV;

            float2 v000 = __half22float2(sAB[i000]);
            float2 v001 = __half22float2(sAB[i000 + 1]);
            float2 v010 = __half22float2(sAB[i010]);
            float2 v011 = __half22float2(sAB[i010 + 1]);
            float2 v100 = __half22float2(sAB[i100]);
            float2 v101 = __half22float2(sAB[i100 + 1]);
            float2 v110 = __half22float2(sAB[i110]);
            float2 v111 = __half22float2(sAB[i110 + 1]);

            float c000 = __half2float(sC[i000]);
            float c001 = __half2float(sC[i000 + 1]);
            float c010 = __half2float(sC[i010]);
            float c011 = __half2float(sC[i010 + 1]);
            float c100 = __half2float(sC[i100]);
            float c101 = __half2float(sC[i100 + 1]);
            float c110 = __half2float(sC[i110]);
            float c111 = __half2float(sC[i110 + 1]);

            float fr0 = 1.0f - fr, fg0 = 1.0f - fg, fb0 = 1.0f - fb;

            float wb0g0 = fb0 * fg0;
            float wb0g1 = fb0 * fg;
            float wb1g0 = fb  * fg0;
            float wb1g1 = fb  * fg;

            float w000 = wb0g0 * fr0, w001 = wb0g0 * fr;
            float w010 = wb0g1 * fr0, w011 = wb0g1 * fr;
            float w100 = wb1g0 * fr0, w101 = wb1g0 * fr;
            float w110 = wb1g1 * fr0, w111 = wb1g1 * fr;

            float a0 = w000 * v000.x;
            float a1 = w000 * v000.y;
            float a2 = w000 * c000;
            a0 = fmaf(w001, v001.x, a0); a1 = fmaf(w001, v001.y, a1); a2 = fmaf(w001, c001, a2);
            a0 = fmaf(w010, v010.x, a0); a1 = fmaf(w010, v010.y, a1); a2 = fmaf(w010, c010, a2);
            a0 = fmaf(w011, v011.x, a0); a1 = fmaf(w011, v011.y, a1); a2 = fmaf(w011, c011, a2);
            a0 = fmaf(w100, v100.x, a0); a1 = fmaf(w100, v100.y, a1); a2 = fmaf(w100, c100, a2);
            a0 = fmaf(w101, v101.x, a0); a1 = fmaf(w101, v101.y, a1); a2 = fmaf(w101, c101, a2);
            a0 = fmaf(w110, v110.x, a0); a1 = fmaf(w110, v110.y, a1); a2 = fmaf(w110, c110, a2);
            a0 = fmaf(w111, v111.x, a0); a1 = fmaf(w111, v111.y, a1); a2 = fmaf(w111, c111, a2);

            o0[k] = a0;
            o1[k] = a1;
            o2[k] = a2;
        }

        {
            int bimg = g >> 21;
            int q    = (g & (GPI - 1)) << 1;
            float* ob = out + (size_t)bimg * 3 * HW + q;
            *(float2*)(ob)          = make_float2(o0[0], o0[1]);
            *(float2*)(ob + HW)     = make_float2(o1[0], o1[1]);
            *(float2*)(ob + 2 * HW) = make_float2(o2[0], o2[1]);
        }

        if (gn >= NGROUPS) break;
        g = gn;
        rv = rvn; gv = gvn; bv = bvn;
    }
}

extern "C" void kernel_launch(void* const* d_in, const int* in_sizes, int n_in,
                              void* d_out, int out_size) {
    const float* x   = (const float*)d_in[0];   // (4, 3, 2048, 2048)
    const float* lut = (const float*)d_in[1];   // (3, 33, 33, 33)
    float* out = (float*)d_out;

    cudaFuncSetAttribute(lut3d_smem_kernel,
                         cudaFuncAttributeMaxDynamicSharedMemorySize, SMEM_BYTES);

    repack_lut_kernel<<<(DIM3 + 255) / 256, 256>>>(lut);

    lut3d_smem_kernel<<<NBLOCKS, NTHREADS, SMEM_BYTES>>>(x, out);
}

// round 7
// speedup vs baseline: 1.5698x; 1.0672x over previous
#include <cuda_runtime.h>
#include <cuda_fp16.h>
#include <cuda_bf16.h>

#define DIMV 33
#define DIM2 (DIMV*DIMV)        // 1089
#define DIM3 (DIMV*DIMV*DIMV)   // 35937
#define HW   (2048*2048)        // 4194304 = 2^22

#define AB_BYTES   (DIM3 * 4)            // half2 per lattice point: 143748 B
#define C_WORDS    ((DIM3 + 1) / 2)      // half array copied as uint32: 17969 words
#define C_BYTES    (C_WORDS * 4)         // 71876 B (padded to even half count)
#define SMEM_BYTES (AB_BYTES + C_BYTES)  // 215624 B  (< 227 KB opt-in limit)

#define NTHREADS 1024
#define NBLOCKS  148

// Global staging for the fp16-compressed, channel-split LUT.
__device__ __half2 g_AB[DIM3];           // (c0, c1) per lattice point
__device__ __half  g_C [DIM3 + 1];       // c2 per lattice point (+pad for 4B copy)

__global__ void repack_lut_kernel(const float* __restrict__ lut) {
    int i = blockIdx.x * blockDim.x + threadIdx.x;
    if (i < DIM3) {
        g_AB[i] = __floats2half2_rn(lut[i], lut[i + DIM3]);
        g_C[i]  = __float2half_rn(lut[i + 2 * DIM3]);
    }
    if (i == 0) g_C[DIM3] = __float2half_rn(0.0f);
}

__global__ void __launch_bounds__(NTHREADS, 1)
lut3d_smem_kernel(const float* __restrict__ x, float* __restrict__ out, int nquads) {
    extern __shared__ char smem[];
    __half2* sAB = (__half2*)smem;
    __half*  sC  = (__half*)(smem + AB_BYTES);

    // Cooperative LUT copy into shared memory (4B granularity).
    {
        const unsigned* gab = (const unsigned*)g_AB;
        unsigned* dab = (unsigned*)sAB;
        for (int i = threadIdx.x; i < DIM3; i += NTHREADS) dab[i] = __ldg(gab + i);
        const unsigned* gc = (const unsigned*)g_C;
        unsigned* dc = (unsigned*)sC;
        for (int i = threadIdx.x; i < C_WORDS; i += NTHREADS) dc[i] = __ldg(gc + i);
    }
    __syncthreads();

    int stride = NBLOCKS * NTHREADS;
    for (int t = blockIdx.x * NTHREADS + threadIdx.x; t < nquads; t += stride) {
        int P = t * 4;                    // global pixel index (quad start)
        int bimg = P >> 22;               // batch (HW = 2^22)
        int q    = P & (HW - 1);

        const float* xb = x + (size_t)bimg * 3 * HW + q;
        float4 rv = __ldcs((const float4*)(xb));
        float4 gv = __ldcs((const float4*)(xb + HW));
        float4 bv = __ldcs((const float4*)(xb + 2 * HW));

        float rr4[4] = {rv.x, rv.y, rv.z, rv.w};
        float gg4[4] = {gv.x, gv.y, gv.z, gv.w};
        float bb4[4] = {bv.x, bv.y, bv.z, bv.w};

        float o0[4], o1[4], o2[4];

        #pragma unroll
        for (int k = 0; k < 4; k++) {
            float rr = rr4[k] * 32.0f;
            float gg = gg4[k] * 32.0f;
            float bb = bb4[k] * 32.0f;

            // x in [0,1) guarantees floor in [0,31]; no clamps needed.
            int r0 = __float2int_rd(rr);
            int g0 = __float2int_rd(gg);
            int b0 = __float2int_rd(bb);

            float fr = rr - (float)r0;
            float fg = gg - (float)g0;
            float fb = bb - (float)b0;

            int i000 = (b0 * DIMV + g0) * DIMV + r0;
            int i010 = i000 + DIMV;
            int i100 = i000 + DIM2;
            int i110 = i100 + DIMV;

            float2 v000 = __half22float2(sAB[i000]);
            float2 v001 = __half22float2(sAB[i000 + 1]);
            float2 v010 = __half22float2(sAB[i010]);
            float2 v011 = __half22float2(sAB[i010 + 1]);
            float2 v100 = __half22float2(sAB[i100]);
            float2 v101 = __half22float2(sAB[i100 + 1]);
            float2 v110 = __half22float2(sAB[i110]);
            float2 v111 = __half22float2(sAB[i110 + 1]);

            float c000 = __half2float(sC[i000]);
            float c001 = __half2float(sC[i000 + 1]);
            float c010 = __half2float(sC[i010]);
            float c011 = __half2float(sC[i010 + 1]);
            float c100 = __half2float(sC[i100]);
            float c101 = __half2float(sC[i100 + 1]);
            float c110 = __half2float(sC[i110]);
            float c111 = __half2float(sC[i110 + 1]);

            float fr0 = 1.0f - fr, fg0 = 1.0f - fg, fb0 = 1.0f - fb;

            float wb0g0 = fb0 * fg0;
            float wb0g1 = fb0 * fg;
            float wb1g0 = fb  * fg0;
            float wb1g1 = fb  * fg;

            float w000 = wb0g0 * fr0, w001 = wb0g0 * fr;
            float w010 = wb0g1 * fr0, w011 = wb0g1 * fr;
            float w100 = wb1g0 * fr0, w101 = wb1g0 * fr;
            float w110 = wb1g1 * fr0, w111 = wb1g1 * fr;

            float a0 = w000 * v000.x;
            float a1 = w000 * v000.y;
            float a2 = w000 * c000;
            a0 = fmaf(w001, v001.x, a0); a1 = fmaf(w001, v001.y, a1); a2 = fmaf(w001, c001, a2);
            a0 = fmaf(w010, v010.x, a0); a1 = fmaf(w010, v010.y, a1); a2 = fmaf(w010, c010, a2);
            a0 = fmaf(w011, v011.x, a0); a1 = fmaf(w011, v011.y, a1); a2 = fmaf(w011, c011, a2);
            a0 = fmaf(w100, v100.x, a0); a1 = fmaf(w100, v100.y, a1); a2 = fmaf(w100, c100, a2);
            a0 = fmaf(w101, v101.x, a0); a1 = fmaf(w101, v101.y, a1); a2 = fmaf(w101, c101, a2);
            a0 = fmaf(w110, v110.x, a0); a1 = fmaf(w110, v110.y, a1); a2 = fmaf(w110, c110, a2);
            a0 = fmaf(w111, v111.x, a0); a1 = fmaf(w111, v111.y, a1); a2 = fmaf(w111, c111, a2);

            o0[k] = a0;
            o1[k] = a1;
            o2[k] = a2;
        }

        float* ob = out + (size_t)bimg * 3 * HW + q;
        __stcs((float4*)(ob),          make_float4(o0[0], o0[1], o0[2], o0[3]));
        __stcs((float4*)(ob + HW),     make_float4(o1[0], o1[1], o1[2], o1[3]));
        __stcs((float4*)(ob + 2 * HW), make_float4(o2[0], o2[1], o2[2], o2[3]));
    }
}

extern "C" void kernel_launch(void* const* d_in, const int* in_sizes, int n_in,
                              void* d_out, int out_size) {
    const float* x   = (const float*)d_in[0];   // (4, 3, 2048, 2048)
    const float* lut = (const float*)d_in[1];   // (3, 33, 33, 33)
    float* out = (float*)d_out;

    cudaFuncSetAttribute(lut3d_smem_kernel,
                         cudaFuncAttributeMaxDynamicSharedMemorySize, SMEM_BYTES);

    repack_lut_kernel<<<(DIM3 + 255) / 256, 256>>>(lut);

    int nquads = (4 * HW) / 4;                  // 4 pixels per thread-iteration
    lut3d_smem_kernel<<<NBLOCKS, NTHREADS, SMEM_BYTES>>>(x, out, nquads);
}